// round 15
// baseline (speedup 1.0000x reference)
#include <cuda_runtime.h>
#include <cstdint>

// Conv1d over W (K=3, pad=1) + roll(+1) on H, as tf32 mma.sync GEMM.
// x: (128,128,28,28) f32, w: (32,128,3) f32 -> out: (128,32,28,28) f32.
//
// Round 14 = round 13 + division-free index math. The cp.async loop and the
// epilogue gather each ran ~7 integer divisions per thread (~30 ALU apiece
// after lowering); both iterate idx += 256, so (co,mw) / (ci,r) advance with
// add-compare-subtract instead (256 = 9*28+4 = 18*14+4).
//  - SoA B fragments (two uint4 arrays, 16B lane stride, coalesced LDG.128)
//  - 8 warps = 2 m32-tiles x 4 k-splits, 4 CTAs/SM, regs 64
//  - A tile via cp.async.cg (36.9KB smem); all-warp gather epilogue

typedef unsigned int u32;

__device__ __align__(16) uint4 g_wB0[4 * 12 * 32];   // [ks][j][lane] = {nt0r0,nt0r1,nt1r0,nt1r1}
__device__ __align__(16) uint4 g_wB1[4 * 12 * 32];   // [ks][j][lane] = {nt2r0,nt2r1,nt3r0,nt3r1}

__device__ __forceinline__ u32 f2tf32(float v) {
    u32 t;
    asm("cvt.rna.tf32.f32 %0, %1;" : "=r"(t) : "f"(v));
    return t;
}
__device__ __forceinline__ uint32_t smem_u32(const void* p) {
    uint32_t a;
    asm("{ .reg .u64 t; cvta.to.shared.u64 t, %1; cvt.u32.u64 %0, t; }" : "=r"(a) : "l"(p));
    return a;
}
__device__ __forceinline__ void cp16(uint32_t dst, const void* src) {
    asm volatile("cp.async.cg.shared.global [%0], [%1], 16;" :: "r"(dst), "l"(src) : "memory");
}

// element (arr, ks, j, lane, e): nt = arr*2 + (e>>1), r = e&1
//   n = 8*nt + (lane>>2), k = ks*96 + 8*j + (lane&3) + 4*r, ci = k&127, kk = k>>7
__global__ void wB_kernel(const float* __restrict__ w) {
    int idx = blockIdx.x * 256 + threadIdx.x;   // 12288 total
    if (idx < 12288) {
        int arr  = idx / 6144;
        int rem  = idx % 6144;
        int e    = rem & 3;
        int lane = (rem >> 2) & 31;
        int t    = rem >> 7;        // 0..47
        int ks   = t / 12;
        int j    = t % 12;
        int nt   = arr * 2 + (e >> 1);
        int r    = e & 1;
        int n    = 8 * nt + (lane >> 2);
        int k    = ks * 96 + 8 * j + (lane & 3) + 4 * r;
        int ci   = k & 127;
        int kk   = k >> 7;
        u32* dst = (u32*)(arr ? g_wB1 : g_wB0);
        dst[(t * 32 + lane) * 4 + e] = f2tf32(w[n * 384 + ci * 3 + kk]);
    }
}

constexpr int RS = 36;                               // A row stride (floats)
constexpr int SMEM_BYTES = 256 * RS * 4 + 64;        // +64B pad for overshoot reads

__global__ __launch_bounds__(256, 4)
void conv_mma_kernel(const float* __restrict__ x, float* __restrict__ out) {
    extern __shared__ __align__(16) u32 smu[];
    const uint32_t sbase = smem_u32(smu);
    const int tid  = threadIdx.x;
    const int b    = blockIdx.y;
    const int h0   = blockIdx.x * 2;

    // ---- async A tile: x[b,ci,h0+hh,4wq..] -> row ci*2+hh, cols 4+4wq (raw f32) ----
    // incremental (ci, r) over i = tid + 256*t : 256 = 18*14 + 4
    const float* xb = x + (size_t)b * 100352;
    {
        int ci = tid / 14;
        int r  = tid % 14;
#pragma unroll
        for (int t = 0; t < 7; t++) {
            int hh = (r >= 7) ? 1 : 0;
            int wq = r - 7 * hh;
            cp16(sbase + ((ci * 2 + hh) * RS + 4 + 4 * wq) * 4,
                 xb + (size_t)(ci * 28 + h0 + hh) * 28 + 4 * wq);
            ci += 18; r += 4;
            if (r >= 14) { r -= 14; ci += 1; }
        }
    }
    asm volatile("cp.async.commit_group;" ::: "memory");

    // halo zeros while copies fly: tile col 3 = x[-1], col 32 = x[28]
    smu[tid * RS + 3]  = 0u;
    smu[tid * RS + 32] = 0u;

    asm volatile("cp.async.wait_group 0;" ::: "memory");
    __syncthreads();

    // ---- main loop: 8 warps = 2 m32-tiles x 4 k-splits (96 k each) ----
    const int warp = tid >> 5;
    const int lane = tid & 31;
    const int mi   = warp & 1;        // m32 tile == hh
    const int ks   = warp >> 1;       // k-split 0..3 (12 k8-steps each)
    const int gid  = lane >> 2;
    const int tig  = lane & 3;

    float c[2][4][4];
#pragma unroll
    for (int mt = 0; mt < 2; mt++)
#pragma unroll
        for (int nt = 0; nt < 4; nt++)
#pragma unroll
            for (int q = 0; q < 4; q++) c[mt][nt][q] = 0.f;

    const u32* As = smu;
    const uint4* B0 = g_wB0 + (ks * 12) * 32 + lane;   // lane stride 16B: coalesced
    const uint4* B1 = g_wB1 + (ks * 12) * 32 + lane;

#pragma unroll
    for (int j = 0; j < 12; j++) {
        int k0  = ks * 96 + j * 8;
        int kk  = k0 >> 7;
        int ci0 = k0 & 127;
        // A[m][k] at (ci*2+hh)*RS + mw + kk + 3 ; ci = ci0+tig(+4), mw = mt*16+gid(+8)
        const u32* ap = As + (ci0 + tig) * (2 * RS) + mi * RS + gid + kk + 3;

        uint4 b0 = B0[j * 32];         // {nt0r0, nt0r1, nt1r0, nt1r1}
        uint4 b1 = B1[j * 32];         // {nt2r0, nt2r1, nt3r0, nt3r1}

        u32 a[2][4];
#pragma unroll
        for (int mt = 0; mt < 2; mt++) {
            const u32* p = ap + mt * 16;
            a[mt][0] = p[0];
            a[mt][1] = p[8];
            a[mt][2] = p[4 * 2 * RS];        // tig+4 -> ci+4
            a[mt][3] = p[4 * 2 * RS + 8];
        }

        u32 bb[4][2] = { {b0.x, b0.y}, {b0.z, b0.w}, {b1.x, b1.y}, {b1.z, b1.w} };
#pragma unroll
        for (int mt = 0; mt < 2; mt++)
#pragma unroll
            for (int nt = 0; nt < 4; nt++) {
                asm volatile(
                    "mma.sync.aligned.m16n8k8.row.col.f32.tf32.tf32.f32 "
                    "{%0,%1,%2,%3}, {%4,%5,%6,%7}, {%8,%9}, {%0,%1,%2,%3};"
                    : "+f"(c[mt][nt][0]), "+f"(c[mt][nt][1]),
                      "+f"(c[mt][nt][2]), "+f"(c[mt][nt][3])
                    : "r"(a[mt][0]), "r"(a[mt][1]), "r"(a[mt][2]), "r"(a[mt][3]),
                      "r"(bb[nt][0]), "r"(bb[nt][1]));
            }
    }

    // ---- all warps dump partials: region (ks*2+mi), layout i*33 + lane ----
    __syncthreads();
    float* red = (float*)smu;   // 8*1056 floats = 33792 B, fits in A region
    {
        float* dst = red + (ks * 2 + mi) * 1056;
#pragma unroll
        for (int i = 0; i < 32; i++)
            dst[i * 33 + lane] = c[i >> 4][(i >> 2) & 3][i & 3];
    }
    __syncthreads();

    // ---- 256-thread gather: sum 4 k-splits, store with roll(+1) on H ----
    // incremental (emi, co, mw) over idx = tid + 256*t : 256 = 9*28 + 4
    float* ob = out + (size_t)b * 25088;
    const int hp0 = (h0 + 1) % 28;     // roll(+1): emi = 0
    const int hp1 = (h0 + 2) % 28;     // roll(+1): emi = 1
    {
        int mw  = tid % 28;
        int co  = tid / 28;            // 0..9 (tid < 256)
        int emi = 0;
#pragma unroll
        for (int t = 0; t < 7; t++) {
            // invert the mma fragment map (shifts/masks only)
            int mt  = mw >> 4;
            int rr  = mw & 15;
            int q2  = rr >> 3;
            int g2  = rr & 7;
            int nt  = co >> 3;
            int tg  = (co & 7) >> 1;
            int q1  = co & 1;
            int ln  = g2 * 4 + tg;
            int fi  = mt * 16 + nt * 4 + q2 * 2 + q1;
            int off = fi * 33 + ln + emi * 1056;
            float v = red[off] + red[off + 2112] + red[off + 4224] + red[off + 6336];
            int hp  = emi ? hp1 : hp0;
            ob[(size_t)co * 784 + hp * 28 + mw] = v;

            mw += 4; co += 9;
            if (mw >= 28) { mw -= 28; co += 1; }
            if (co >= 32) { co -= 32; emi = 1; }
        }
    }
}

extern "C" void kernel_launch(void* const* d_in, const int* in_sizes, int n_in,
                              void* d_out, int out_size) {
    const float* x = (const float*)d_in[0];
    const float* w = (const float*)d_in[1];
    float* out = (float*)d_out;

    cudaFuncSetAttribute(conv_mma_kernel,
                         cudaFuncAttributeMaxDynamicSharedMemorySize, SMEM_BYTES);

    wB_kernel<<<48, 256>>>(w);
    conv_mma_kernel<<<dim3(14, 128), 256, SMEM_BYTES>>>(x, out);
}